// round 1
// baseline (speedup 1.0000x reference)
#include <cuda_runtime.h>

#define S 2048
#define B 32
#define H 1024

// Scratch (no allocation allowed in kernel_launch)
__device__ float g_v[B * H];        // v[b,h] = sum_k dec[b,k] * W[k,h]
__device__ float g_energy[B * S];   // energies[b,s]

// ---------------------------------------------------------------------------
__global__ void init_v_kernel() {
    int i = blockIdx.x * blockDim.x + threadIdx.x;
    if (i < B * H) g_v[i] = 0.0f;
}

// ---------------------------------------------------------------------------
// v[b,h] += sum_{k in chunk} dec[b,k] * W[k,h]
// grid: (H/K1_TH, H/K1_KC), block K1_TH threads (one h per thread)
#define K1_TH 128
#define K1_KC 64
__global__ __launch_bounds__(K1_TH) void proj_kernel(
    const float* __restrict__ dec,   // [B, H]
    const float* __restrict__ W)     // [H, H], W[k*H + h]
{
    __shared__ float s_dec[B][K1_KC];
    const int h  = blockIdx.x * K1_TH + threadIdx.x;
    const int k0 = blockIdx.y * K1_KC;

    // stage dec[:, k0:k0+K1_KC] -> smem (B*K1_KC = 2048 floats)
    for (int i = threadIdx.x; i < B * K1_KC; i += K1_TH) {
        int b = i / K1_KC, k = i % K1_KC;
        s_dec[b][k] = dec[b * H + k0 + k];
    }
    __syncthreads();

    float acc[B];
#pragma unroll
    for (int b = 0; b < B; b++) acc[b] = 0.0f;

    for (int k = 0; k < K1_KC; k++) {
        float w = W[(size_t)(k0 + k) * H + h];   // coalesced across threads
#pragma unroll
        for (int b = 0; b < B; b++)
            acc[b] = fmaf(s_dec[b][k], w, acc[b]);
    }

#pragma unroll
    for (int b = 0; b < B; b++)
        atomicAdd(&g_v[b * H + h], acc[b]);
}

// ---------------------------------------------------------------------------
// energies[b,s] = v[b] . enc[s,b,:]   (dominant, streams 256 MB)
// grid: (S/K2_WARPS, B), block = 32*K2_WARPS; one warp per s-row
#define K2_WARPS 8
__global__ __launch_bounds__(32 * K2_WARPS) void energy_kernel(
    const float* __restrict__ enc)   // [S, B, H]
{
    __shared__ float4 s_v[H / 4];
    const int b = blockIdx.y;

    const float4* vb = reinterpret_cast<const float4*>(&g_v[b * H]);
    for (int i = threadIdx.x; i < H / 4; i += blockDim.x) s_v[i] = vb[i];
    __syncthreads();

    const int warp = threadIdx.x >> 5;
    const int lane = threadIdx.x & 31;
    const int s = blockIdx.x * K2_WARPS + warp;

    const float4* e =
        reinterpret_cast<const float4*>(&enc[((size_t)s * B + b) * (size_t)H]);

    float acc = 0.0f;
#pragma unroll
    for (int j = 0; j < (H / 4) / 32; j++) {   // 8 iterations of float4
        float4 ev = e[lane + j * 32];
        float4 vv = s_v[lane + j * 32];
        acc = fmaf(ev.x, vv.x, acc);
        acc = fmaf(ev.y, vv.y, acc);
        acc = fmaf(ev.z, vv.z, acc);
        acc = fmaf(ev.w, vv.w, acc);
    }

#pragma unroll
    for (int o = 16; o > 0; o >>= 1)
        acc += __shfl_down_sync(0xffffffffu, acc, o);

    if (lane == 0) g_energy[b * S + s] = acc;
}

// ---------------------------------------------------------------------------
// softmax over s for each b. grid: B blocks of 256 threads, 8 elems/thread.
#define K3_TH 256
__global__ __launch_bounds__(K3_TH) void softmax_kernel(float* __restrict__ out)
{
    __shared__ float red[K3_TH / 32];
    const int b = blockIdx.x;
    const int tid = threadIdx.x;
    const int lane = tid & 31, warp = tid >> 5;
    const float* e = &g_energy[b * S];

    float vals[S / K3_TH];
    float m = -1e30f;
#pragma unroll
    for (int j = 0; j < S / K3_TH; j++) {
        vals[j] = e[tid + j * K3_TH];
        m = fmaxf(m, vals[j]);
    }
#pragma unroll
    for (int o = 16; o > 0; o >>= 1)
        m = fmaxf(m, __shfl_xor_sync(0xffffffffu, m, o));
    if (lane == 0) red[warp] = m;
    __syncthreads();
#pragma unroll
    for (int w = 0; w < K3_TH / 32; w++) m = fmaxf(m, red[w]);
    __syncthreads();

    float sum = 0.0f;
#pragma unroll
    for (int j = 0; j < S / K3_TH; j++) {
        vals[j] = __expf(vals[j] - m);
        sum += vals[j];
    }
#pragma unroll
    for (int o = 16; o > 0; o >>= 1)
        sum += __shfl_xor_sync(0xffffffffu, sum, o);
    if (lane == 0) red[warp] = sum;
    __syncthreads();
    float total = 0.0f;
#pragma unroll
    for (int w = 0; w < K3_TH / 32; w++) total += red[w];

    const float inv = __frcp_rn(total);
#pragma unroll
    for (int j = 0; j < S / K3_TH; j++)
        out[b * S + tid + j * K3_TH] = vals[j] * inv;
}

// ---------------------------------------------------------------------------
extern "C" void kernel_launch(void* const* d_in, const int* in_sizes, int n_in,
                              void* d_out, int out_size)
{
    const float* dec = (const float*)d_in[0];   // rnn_outputs [1,B,H]
    const float* enc = (const float*)d_in[1];   // encoder_outputs [S,B,H]
    const float* W   = (const float*)d_in[2];   // W_attn [H,H]
    // d_in[3] = b_attn: constant over s per batch -> cancelled by softmax.
    float* out = (float*)d_out;                 // [B,S] float32

    init_v_kernel<<<(B * H + 255) / 256, 256>>>();
    proj_kernel<<<dim3(H / K1_TH, H / K1_KC), K1_TH>>>(dec, W);
    energy_kernel<<<dim3(S / K2_WARPS, B), 32 * K2_WARPS>>>(enc);
    softmax_kernel<<<B, K3_TH>>>(out);
}

// round 2
// speedup vs baseline: 1.4255x; 1.4255x over previous
#include <cuda_runtime.h>

#define S 2048
#define B 32
#define H 1024

// Scratch (no allocation allowed in kernel_launch)
__device__ float g_v[B * H];        // v[b,h] = sum_k dec[b,k] * W[k,h]
__device__ float g_energy[B * S];   // energies[b,s]

// ---------------------------------------------------------------------------
__global__ void init_v_kernel() {
    int i = blockIdx.x * blockDim.x + threadIdx.x;
    if (i < B * H) g_v[i] = 0.0f;
}

// ---------------------------------------------------------------------------
// v[b,h] += sum_{k in chunk} dec[b,k] * W[k,h]
// grid: (H/K1_TH, H/K1_KC) = (8, 32) = 256 blocks; one h per thread.
#define K1_TH 128
#define K1_KC 32
__global__ __launch_bounds__(K1_TH) void proj_kernel(
    const float* __restrict__ dec,   // [B, H]
    const float* __restrict__ W)     // [H, H], W[k*H + h]
{
    __shared__ float s_dec[B][K1_KC];
    const int h  = blockIdx.x * K1_TH + threadIdx.x;
    const int k0 = blockIdx.y * K1_KC;

    // stage dec[:, k0:k0+K1_KC] -> smem (B*K1_KC = 1024 floats)
    for (int i = threadIdx.x; i < B * K1_KC; i += K1_TH) {
        int b = i / K1_KC, k = i % K1_KC;
        s_dec[b][k] = dec[b * H + k0 + k];
    }
    __syncthreads();

    float acc[B];
#pragma unroll
    for (int b = 0; b < B; b++) acc[b] = 0.0f;

    // unroll-by-8: batch 8 independent W loads (MLP=8) before the FMA burst
#pragma unroll
    for (int kk = 0; kk < K1_KC; kk += 8) {
        float w[8];
#pragma unroll
        for (int u = 0; u < 8; u++)
            w[u] = __ldg(&W[(size_t)(k0 + kk + u) * H + h]);
#pragma unroll
        for (int u = 0; u < 8; u++) {
#pragma unroll
            for (int b = 0; b < B; b++)
                acc[b] = fmaf(s_dec[b][kk + u], w[u], acc[b]);
        }
    }

#pragma unroll
    for (int b = 0; b < B; b++)
        atomicAdd(&g_v[b * H + h], acc[b]);
}

// ---------------------------------------------------------------------------
// energies[b,s] = v[b] . enc[s,b,:]   (dominant, streams 256 MB)
// One warp handles TWO s-rows (MLP = 16 float4 loads in flight per thread).
// grid: (S / (K2_WARPS*2), B), block = 32*K2_WARPS
#define K2_WARPS 8
#define K2_ROWS (K2_WARPS * 2)
__global__ __launch_bounds__(32 * K2_WARPS) void energy_kernel(
    const float* __restrict__ enc)   // [S, B, H]
{
    __shared__ float4 s_v[H / 4];
    const int b = blockIdx.y;

    const float4* vb = reinterpret_cast<const float4*>(&g_v[b * H]);
    for (int i = threadIdx.x; i < H / 4; i += blockDim.x) s_v[i] = vb[i];
    __syncthreads();

    const int warp = threadIdx.x >> 5;
    const int lane = threadIdx.x & 31;
    const int s0 = blockIdx.x * K2_ROWS + warp;          // row 1
    const int s1 = s0 + K2_WARPS;                        // row 2

    const float4* e0 =
        reinterpret_cast<const float4*>(&enc[((size_t)s0 * B + b) * (size_t)H]);
    const float4* e1 =
        reinterpret_cast<const float4*>(&enc[((size_t)s1 * B + b) * (size_t)H]);

    float acc0 = 0.0f, acc1 = 0.0f;
#pragma unroll
    for (int j = 0; j < (H / 4) / 32; j++) {   // 8 float4 iterations per row
        float4 a = __ldcs(&e0[lane + j * 32]); // streaming: don't pollute L2
        float4 c = __ldcs(&e1[lane + j * 32]);
        float4 vv = s_v[lane + j * 32];
        acc0 = fmaf(a.x, vv.x, acc0);
        acc0 = fmaf(a.y, vv.y, acc0);
        acc0 = fmaf(a.z, vv.z, acc0);
        acc0 = fmaf(a.w, vv.w, acc0);
        acc1 = fmaf(c.x, vv.x, acc1);
        acc1 = fmaf(c.y, vv.y, acc1);
        acc1 = fmaf(c.z, vv.z, acc1);
        acc1 = fmaf(c.w, vv.w, acc1);
    }

#pragma unroll
    for (int o = 16; o > 0; o >>= 1) {
        acc0 += __shfl_down_sync(0xffffffffu, acc0, o);
        acc1 += __shfl_down_sync(0xffffffffu, acc1, o);
    }

    if (lane == 0) {
        g_energy[b * S + s0] = acc0;
        g_energy[b * S + s1] = acc1;
    }
}

// ---------------------------------------------------------------------------
// softmax over s for each b. grid: B blocks of 1024 threads, 2 elems/thread.
#define K3_TH 1024
__global__ __launch_bounds__(K3_TH) void softmax_kernel(float* __restrict__ out)
{
    __shared__ float red[K3_TH / 32];
    const int b = blockIdx.x;
    const int tid = threadIdx.x;
    const int lane = tid & 31, warp = tid >> 5;
    const float* e = &g_energy[b * S];

    float vals[S / K3_TH];
    float m = -1e30f;
#pragma unroll
    for (int j = 0; j < S / K3_TH; j++) {
        vals[j] = e[tid + j * K3_TH];
        m = fmaxf(m, vals[j]);
    }
#pragma unroll
    for (int o = 16; o > 0; o >>= 1)
        m = fmaxf(m, __shfl_xor_sync(0xffffffffu, m, o));
    if (lane == 0) red[warp] = m;
    __syncthreads();
#pragma unroll
    for (int w = 0; w < K3_TH / 32; w++) m = fmaxf(m, red[w]);
    __syncthreads();

    float sum = 0.0f;
#pragma unroll
    for (int j = 0; j < S / K3_TH; j++) {
        vals[j] = __expf(vals[j] - m);
        sum += vals[j];
    }
#pragma unroll
    for (int o = 16; o > 0; o >>= 1)
        sum += __shfl_xor_sync(0xffffffffu, sum, o);
    if (lane == 0) red[warp] = sum;
    __syncthreads();
    float total = 0.0f;
#pragma unroll
    for (int w = 0; w < K3_TH / 32; w++) total += red[w];

    const float inv = __frcp_rn(total);
#pragma unroll
    for (int j = 0; j < S / K3_TH; j++)
        out[b * S + tid + j * K3_TH] = vals[j] * inv;
}

// ---------------------------------------------------------------------------
extern "C" void kernel_launch(void* const* d_in, const int* in_sizes, int n_in,
                              void* d_out, int out_size)
{
    const float* dec = (const float*)d_in[0];   // rnn_outputs [1,B,H]
    const float* enc = (const float*)d_in[1];   // encoder_outputs [S,B,H]
    const float* W   = (const float*)d_in[2];   // W_attn [H,H]
    // d_in[3] = b_attn: constant over s per batch -> cancelled by softmax.
    float* out = (float*)d_out;                 // [B,S] float32

    init_v_kernel<<<(B * H + 255) / 256, 256>>>();
    proj_kernel<<<dim3(H / K1_TH, H / K1_KC), K1_TH>>>(dec, W);
    energy_kernel<<<dim3(S / K2_ROWS, B), 32 * K2_WARPS>>>(enc);
    softmax_kernel<<<B, K3_TH>>>(out);
}